// round 1
// baseline (speedup 1.0000x reference)
#include <cuda_runtime.h>
#include <math_constants.h>

#define BB 2
#define HH 256
#define WW 256
#define PTS 64
#define IMP 64
#define NRAYS (BB*HH*WW)          // 131072
#define NEARP 0.1f
#define FARP  2.0f
#define DSTEP ((FARP-NEARP)/63.0f)
#define FOCAL 4.2f

#define OFS_C 0
#define OFS_F (BB*3*HH*WW)        // 393216
#define OFS_D (2*BB*3*HH*WW)      // 786432

__device__ int g_min_bits;
__device__ int g_max_bits;

__device__ __forceinline__ float sigm(float x) {
    return 1.0f / (1.0f + __expf(-x));
}

__global__ void init_kernel() {
    g_min_bits = 0x7f800000;  // +inf
    g_max_bits = 0;           // 0.0f (ray depths are strictly positive)
}

__global__ __launch_bounds__(128) void render_kernel(
    const float* __restrict__ tm,   // (B,3,4)
    const float* __restrict__ Wq,   // (6,4)
    float* __restrict__ out)
{
    int r = blockIdx.x * blockDim.x + threadIdx.x;
    if (r >= NRAYS) return;
    int b = r >> 16;
    int n = r & 65535;
    int iy = n >> 8;       // image row
    int jx = n & 255;      // image col

    // camera dir: x = linspace(1,-1,H)[jx]/F, y = linspace(1,-1,W)[iy]/F, z=1
    float cx = fmaf((float)jx, -2.0f / 255.0f, 1.0f) * (1.0f / FOCAL);
    float cy = fmaf((float)iy, -2.0f / 255.0f, 1.0f) * (1.0f / FOCAL);

    const float* T = tm + b * 12;
    float dx = T[0] * cx + T[1] * cy + T[2];
    float dy = T[4] * cx + T[5] * cy + T[6];
    float dz = T[8] * cx + T[9] * cy + T[10];
    float ox = T[3], oy = T[7], oz = T[11];

    // feat(depth)[c] = base[c] + depth * kk[c]
    float base[4], kk[4];
#pragma unroll
    for (int c = 0; c < 4; c++) {
        base[c] = ox * Wq[0 * 4 + c] + oy * Wq[1 * 4 + c] + oz * Wq[2 * 4 + c]
                + dx * Wq[3 * 4 + c] + dy * Wq[4 * 4 + c] + dz * Wq[5 * 4 + c];
        kk[c]   = dx * Wq[0 * 4 + c] + dy * Wq[1 * 4 + c] + dz * Wq[2 * 4 + c];
    }

    float cdf[PTS];   // unnormalized cumsum of (w + 1e-5)
    float fd[IMP];    // fine (importance) depths, sorted by construction

    // ---------------- Pass 1: coarse ray march + cdf build ----------------
    float absorption = 1.0f;
    float a0 = 0.0f, a1 = 0.0f, a2 = 0.0f;
    float cum = 0.0f;
#pragma unroll 4
    for (int p = 0; p < PTS; p++) {
        float d = NEARP + p * DSTEP;
        float op = sigm(fmaf(d, kk[0], base[0]));
        float v0 = sigm(fmaf(d, kk[1], base[1]));
        float v1 = sigm(fmaf(d, kk[2], base[2]));
        float v2 = sigm(fmaf(d, kk[3], base[3]));
        float w = op * absorption;
        absorption *= (1.0f - op);
        a0 = fmaf(w, v0, a0);
        a1 = fmaf(w, v1, a1);
        a2 = fmaf(w, v2, a2);
        cum += w + 1e-5f;
        cdf[p] = cum;
    }
    out[OFS_C + ((b * 3 + 0) << 16) + n] = a0;
    out[OFS_C + ((b * 3 + 1) << 16) + n] = a1;
    out[OFS_C + ((b * 3 + 2) << 16) + n] = a2;

    float inv_total = 1.0f / cum;

    // ---------------- Pass 2: inverse-CDF sampling (streaming searchsorted) ----------------
    {
        int jp = 0;
        float prev_bin = 0.0f;
#pragma unroll 1
        for (int k = 0; k <= IMP; k++) {
            float u = (float)k * (1.0f / 64.0f);
            while (jp < PTS && cdf[jp] * inv_total <= u) jp++;
            int below = (jp - 1 < 0) ? 0 : (jp - 1);
            int above = (jp > PTS - 1) ? (PTS - 1) : jp;
            float c0 = cdf[below] * inv_total;
            float c1 = cdf[above] * inv_total;
            float d0 = NEARP + below * DSTEP;
            float d1 = NEARP + above * DSTEP;
            float dd = c1 - c0;
            float denom = (dd < 1e-8f) ? 1.0f : dd;
            float t = (u - c0) / denom;
            t = fminf(fmaxf(t, 0.0f), 1.0f);
            float bin = fmaf(t, d1 - d0, d0);
            if (k > 0) fd[k - 1] = 0.5f * (prev_bin + bin);
            prev_bin = bin;
        }
    }

    // ---------------- Pass 3: merged (coarse ∪ fine) ray march ----------------
    absorption = 1.0f;
    a0 = a1 = a2 = 0.0f;
    float wsum = 0.0f, dsum = 0.0f;
    int ic = 0, jf = 0;
#pragma unroll 1
    for (int m = 0; m < PTS + IMP; m++) {
        float dc = (ic < PTS) ? (NEARP + ic * DSTEP) : CUDART_INF_F;
        float df = (jf < IMP) ? fd[jf] : CUDART_INF_F;
        float d;
        if (dc <= df) { d = dc; ic++; }   // stable: coarse first on ties (values identical anyway)
        else          { d = df; jf++; }
        float op = sigm(fmaf(d, kk[0], base[0]));
        float v0 = sigm(fmaf(d, kk[1], base[1]));
        float v1 = sigm(fmaf(d, kk[2], base[2]));
        float v2 = sigm(fmaf(d, kk[3], base[3]));
        float w = op * absorption;
        absorption *= (1.0f - op);
        a0 = fmaf(w, v0, a0);
        a1 = fmaf(w, v1, a1);
        a2 = fmaf(w, v2, a2);
        wsum += w;
        dsum = fmaf(w, d, dsum);
    }
    out[OFS_F + ((b * 3 + 0) << 16) + n] = a0;
    out[OFS_F + ((b * 3 + 1) << 16) + n] = a1;
    out[OFS_F + ((b * 3 + 2) << 16) + n] = a2;

    // ray depth: sum(w*d) + (1 - clip(sum w,0,1)) * max(d_all) [= FAR exactly]
    float f_accum_op = fminf(wsum, 1.0f);
    float rd = dsum + (1.0f - f_accum_op) * FARP;
    out[OFS_D + (b << 16) + n] = rd;

    // global min/max reduction: warp shuffle then int-bit atomics (rd > 0)
    float mn = rd, mx = rd;
#pragma unroll
    for (int o = 16; o > 0; o >>= 1) {
        mn = fminf(mn, __shfl_xor_sync(0xffffffffu, mn, o));
        mx = fmaxf(mx, __shfl_xor_sync(0xffffffffu, mx, o));
    }
    if ((threadIdx.x & 31) == 0) {
        atomicMin(&g_min_bits, __float_as_int(mn));
        atomicMax(&g_max_bits, __float_as_int(mx));
    }
}

__global__ __launch_bounds__(256) void norm_kernel(float* __restrict__ out) {
    float mn = __int_as_float(g_min_bits);
    float mx = __int_as_float(g_max_bits);
    float inv = 1.0f / (mx - mn);
    int idx = blockIdx.x * blockDim.x + threadIdx.x;
    if (idx < NRAYS) {
        float v = out[OFS_D + idx];
        out[OFS_D + idx] = (v - mn) * inv;
    }
}

extern "C" void kernel_launch(void* const* d_in, const int* in_sizes, int n_in,
                              void* d_out, int out_size) {
    const float* tm = (const float*)d_in[0];   // transform_matrix (2,3,4)
    const float* Wq = (const float*)d_in[1];   // W_query (6,4)
    float* out = (float*)d_out;

    init_kernel<<<1, 1>>>();
    render_kernel<<<NRAYS / 128, 128>>>(tm, Wq, out);
    norm_kernel<<<(NRAYS + 255) / 256, 256>>>(out);
}

// round 3
// speedup vs baseline: 1.6421x; 1.6421x over previous
#include <cuda_runtime.h>
#include <math_constants.h>

#define BB 2
#define HH 256
#define WW 256
#define PTS 64
#define IMP 64
#define NRAYS (BB*HH*WW)          // 131072
#define NEARP 0.1f
#define FARP  2.0f
#define DSTEP ((FARP-NEARP)/63.0f)
#define FOCAL 4.2f

#define OFS_C 0
#define OFS_F (BB*3*HH*WW)        // 393216
#define OFS_D (2*BB*3*HH*WW)      // 786432

__device__ int g_min_bits;
__device__ int g_max_bits;

__device__ __forceinline__ float tanh_approx(float x) {
    float y;
    asm("tanh.approx.f32 %0, %1;" : "=f"(y) : "f"(x));
    return y;
}

// sigmoid(x) = 0.5*tanh(0.5*x) + 0.5   -> 1 MUFU.TANH + 2 FMA (vs EX2+RCP = 2 MUFU)
__device__ __forceinline__ float sigm(float x) {
    return fmaf(tanh_approx(0.5f * x), 0.5f, 0.5f);
}

__global__ void init_kernel() {
    g_min_bits = 0x7f800000;  // +inf
    g_max_bits = 0;           // 0.0f (ray depths are strictly positive)
}

__global__ __launch_bounds__(128) void render_kernel(
    const float* __restrict__ tm,   // (B,3,4)
    const float* __restrict__ Wq,   // (6,4)
    float* __restrict__ out)
{
    int r = blockIdx.x * blockDim.x + threadIdx.x;
    if (r >= NRAYS) return;
    int b = r >> 16;
    int n = r & 65535;
    int iy = n >> 8;       // image row
    int jx = n & 255;      // image col

    // camera dir: x = linspace(1,-1,H)[jx]/F, y = linspace(1,-1,W)[iy]/F, z=1
    float cx = fmaf((float)jx, -2.0f / 255.0f, 1.0f) * (1.0f / FOCAL);
    float cy = fmaf((float)iy, -2.0f / 255.0f, 1.0f) * (1.0f / FOCAL);

    const float* T = tm + b * 12;
    float dx = __ldg(T + 0) * cx + __ldg(T + 1) * cy + __ldg(T + 2);
    float dy = __ldg(T + 4) * cx + __ldg(T + 5) * cy + __ldg(T + 6);
    float dz = __ldg(T + 8) * cx + __ldg(T + 9) * cy + __ldg(T + 10);
    float ox = __ldg(T + 3), oy = __ldg(T + 7), oz = __ldg(T + 11);

    // feat(depth)[c] = base[c] + depth * kk[c]
    float base[4], kk[4];
#pragma unroll
    for (int c = 0; c < 4; c++) {
        base[c] = ox * __ldg(Wq + 0 * 4 + c) + oy * __ldg(Wq + 1 * 4 + c) + oz * __ldg(Wq + 2 * 4 + c)
                + dx * __ldg(Wq + 3 * 4 + c) + dy * __ldg(Wq + 4 * 4 + c) + dz * __ldg(Wq + 5 * 4 + c);
        kk[c]   = dx * __ldg(Wq + 0 * 4 + c) + dy * __ldg(Wq + 1 * 4 + c) + dz * __ldg(Wq + 2 * 4 + c);
    }

    float cdf[PTS];   // unnormalized cumsum of (w + 1e-5)
    float fd[IMP];    // fine (importance) depths, sorted by construction

    // ---------------- Pass 1: coarse ray march + cdf build ----------------
    float absorption = 1.0f;
    float a0 = 0.0f, a1 = 0.0f, a2 = 0.0f;
    float cum = 0.0f;
#pragma unroll 4
    for (int p = 0; p < PTS; p++) {
        float d = NEARP + p * DSTEP;
        float op = sigm(fmaf(d, kk[0], base[0]));
        float v0 = sigm(fmaf(d, kk[1], base[1]));
        float v1 = sigm(fmaf(d, kk[2], base[2]));
        float v2 = sigm(fmaf(d, kk[3], base[3]));
        float w = op * absorption;
        absorption *= (1.0f - op);
        a0 = fmaf(w, v0, a0);
        a1 = fmaf(w, v1, a1);
        a2 = fmaf(w, v2, a2);
        cum += w + 1e-5f;
        cdf[p] = cum;
    }
    out[OFS_C + ((b * 3 + 0) << 16) + n] = a0;
    out[OFS_C + ((b * 3 + 1) << 16) + n] = a1;
    out[OFS_C + ((b * 3 + 2) << 16) + n] = a2;

    float inv_total = 1.0f / cum;

    // ---------------- Pass 2: inverse-CDF sampling (streaming searchsorted) ----------------
    {
        int jp = 0;
        float prev_bin = 0.0f;
#pragma unroll 1
        for (int k = 0; k <= IMP; k++) {
            float u = (float)k * (1.0f / 64.0f);
            while (jp < PTS && cdf[jp] * inv_total <= u) jp++;
            int below = (jp - 1 < 0) ? 0 : (jp - 1);
            int above = (jp > PTS - 1) ? (PTS - 1) : jp;
            float c0 = cdf[below] * inv_total;
            float c1 = cdf[above] * inv_total;
            float d0 = NEARP + below * DSTEP;
            float d1 = NEARP + above * DSTEP;
            float dd = c1 - c0;
            float denom = (dd < 1e-8f) ? 1.0f : dd;
            float t = (u - c0) / denom;
            t = fminf(fmaxf(t, 0.0f), 1.0f);
            float bin = fmaf(t, d1 - d0, d0);
            if (k > 0) fd[k - 1] = 0.5f * (prev_bin + bin);
            prev_bin = bin;
        }
    }

    // ---------------- Pass 3: merged (coarse ∪ fine) ray march ----------------
    absorption = 1.0f;
    a0 = a1 = a2 = 0.0f;
    float wsum = 0.0f, dsum = 0.0f;
    int ic = 0, jf = 0;
#pragma unroll 1
    for (int m = 0; m < PTS + IMP; m++) {
        float dc = (ic < PTS) ? (NEARP + ic * DSTEP) : CUDART_INF_F;
        float df = (jf < IMP) ? fd[jf] : CUDART_INF_F;
        float d;
        if (dc <= df) { d = dc; ic++; }   // stable: coarse first on ties (values identical anyway)
        else          { d = df; jf++; }
        float op = sigm(fmaf(d, kk[0], base[0]));
        float v0 = sigm(fmaf(d, kk[1], base[1]));
        float v1 = sigm(fmaf(d, kk[2], base[2]));
        float v2 = sigm(fmaf(d, kk[3], base[3]));
        float w = op * absorption;
        absorption *= (1.0f - op);
        a0 = fmaf(w, v0, a0);
        a1 = fmaf(w, v1, a1);
        a2 = fmaf(w, v2, a2);
        wsum += w;
        dsum = fmaf(w, d, dsum);
    }
    out[OFS_F + ((b * 3 + 0) << 16) + n] = a0;
    out[OFS_F + ((b * 3 + 1) << 16) + n] = a1;
    out[OFS_F + ((b * 3 + 2) << 16) + n] = a2;

    // ray depth: sum(w*d) + (1 - clip(sum w,0,1)) * max(d_all) [= FAR exactly]
    float f_accum_op = fminf(wsum, 1.0f);
    float rd = dsum + (1.0f - f_accum_op) * FARP;
    out[OFS_D + (b << 16) + n] = rd;

    // global min/max reduction: warp shuffle then int-bit atomics (rd > 0)
    float mn = rd, mx = rd;
#pragma unroll
    for (int o = 16; o > 0; o >>= 1) {
        mn = fminf(mn, __shfl_xor_sync(0xffffffffu, mn, o));
        mx = fmaxf(mx, __shfl_xor_sync(0xffffffffu, mx, o));
    }
    if ((threadIdx.x & 31) == 0) {
        atomicMin(&g_min_bits, __float_as_int(mn));
        atomicMax(&g_max_bits, __float_as_int(mx));
    }
}

__global__ __launch_bounds__(256) void norm_kernel(float* __restrict__ out) {
    float mn = __int_as_float(g_min_bits);
    float mx = __int_as_float(g_max_bits);
    float inv = 1.0f / (mx - mn);
    int idx = blockIdx.x * blockDim.x + threadIdx.x;
    if (idx < NRAYS) {
        float v = out[OFS_D + idx];
        out[OFS_D + idx] = (v - mn) * inv;
    }
}

extern "C" void kernel_launch(void* const* d_in, const int* in_sizes, int n_in,
                              void* d_out, int out_size) {
    const float* tm = (const float*)d_in[0];   // transform_matrix (2,3,4)
    const float* Wq = (const float*)d_in[1];   // W_query (6,4)
    float* out = (float*)d_out;

    init_kernel<<<1, 1>>>();
    render_kernel<<<NRAYS / 128, 128>>>(tm, Wq, out);
    norm_kernel<<<(NRAYS + 255) / 256, 256>>>(out);
}